// round 2
// baseline (speedup 1.0000x reference)
#include <cuda_runtime.h>
#include <float.h>

// Problem constants
#define BB 4
#define LL 4096
#define DH 1024
#define TT 1024
#define DG 768
#define PP 256

// Scratch (no cudaMalloc allowed): K [B,L,P], Q [B,T,P], S/alpha [B,T,L]
__device__ float g_K[(size_t)BB * LL * PP];   // 16 MB
__device__ float g_Q[(size_t)BB * TT * PP];   //  4 MB
__device__ float g_S[(size_t)BB * TT * LL];   // 64 MB

// ---------------------------------------------------------------------------
// Tiled SGEMM. C[M,N] = scale * A[M,K] * op(B)
//   BT=true : B is [N,K] row-major (NT gemm, both operands K-contiguous)
//   BT=false: B is [K,N] row-major (NN gemm)
// Optional per-column mask (int32, nonzero => set -FLT_MAX), for the logits.
// All dims assumed multiples of tile sizes (true for this problem).
// ---------------------------------------------------------------------------
#define BM 128
#define BN 128
#define BKD 8
#define TM 8
#define TN 8
// 256 threads = (BM/TM)*(BN/TN)

template <bool BT>
__global__ __launch_bounds__(256)
void sgemm_kernel(const float* __restrict__ A,
                  const float* __restrict__ B,
                  float* __restrict__ C,
                  int M, int N, int K,
                  long strideA, long strideB, long strideC,
                  float scale,
                  const int* __restrict__ mask,
                  long maskStride)
{
    const int b = blockIdx.z;
    A += (long)b * strideA;
    B += (long)b * strideB;
    C += (long)b * strideC;
    if (mask) mask += (long)b * maskStride;

    __shared__ float As[BKD][BM];
    __shared__ float Bs[BKD][BN];

    const int tid = threadIdx.x;
    const int blockRow = blockIdx.y * BM;
    const int blockCol = blockIdx.x * BN;

    const int tRow = (tid / (BN / TN)) * TM;   // 0..120
    const int tCol = (tid % (BN / TN)) * TN;   // 0..120

    // A-tile loader: 128x8 floats, one float4 per thread
    const int aRow = tid >> 1;           // 0..127
    const int aCol = (tid & 1) * 4;      // 0 or 4
    // B-tile loader (NT): same shape as A
    const int bRowNT = tid >> 1;
    const int bColNT = (tid & 1) * 4;
    // B-tile loader (NN): 8x128 floats
    const int bRowNN = tid >> 5;         // 0..7
    const int bColNN = (tid & 31) * 4;   // 0..124

    float acc[TM][TN];
#pragma unroll
    for (int i = 0; i < TM; i++)
#pragma unroll
        for (int j = 0; j < TN; j++) acc[i][j] = 0.0f;

    for (int k0 = 0; k0 < K; k0 += BKD) {
        // Load A tile (transposed into As[k][m])
        float4 av = *reinterpret_cast<const float4*>(
            &A[(long)(blockRow + aRow) * K + k0 + aCol]);
        As[aCol + 0][aRow] = av.x;
        As[aCol + 1][aRow] = av.y;
        As[aCol + 2][aRow] = av.z;
        As[aCol + 3][aRow] = av.w;

        if (BT) {
            float4 bv = *reinterpret_cast<const float4*>(
                &B[(long)(blockCol + bRowNT) * K + k0 + bColNT]);
            Bs[bColNT + 0][bRowNT] = bv.x;
            Bs[bColNT + 1][bRowNT] = bv.y;
            Bs[bColNT + 2][bRowNT] = bv.z;
            Bs[bColNT + 3][bRowNT] = bv.w;
        } else {
            float4 bv = *reinterpret_cast<const float4*>(
                &B[(long)(k0 + bRowNN) * N + blockCol + bColNN]);
            *reinterpret_cast<float4*>(&Bs[bRowNN][bColNN]) = bv;
        }
        __syncthreads();

#pragma unroll
        for (int k = 0; k < BKD; k++) {
            float4 a0 = *reinterpret_cast<const float4*>(&As[k][tRow]);
            float4 a1 = *reinterpret_cast<const float4*>(&As[k][tRow + 4]);
            float4 b0 = *reinterpret_cast<const float4*>(&Bs[k][tCol]);
            float4 b1 = *reinterpret_cast<const float4*>(&Bs[k][tCol + 4]);
            float ra[TM] = {a0.x, a0.y, a0.z, a0.w, a1.x, a1.y, a1.z, a1.w};
            float rb[TN] = {b0.x, b0.y, b0.z, b0.w, b1.x, b1.y, b1.z, b1.w};
#pragma unroll
            for (int i = 0; i < TM; i++)
#pragma unroll
                for (int j = 0; j < TN; j++)
                    acc[i][j] = fmaf(ra[i], rb[j], acc[i][j]);
        }
        __syncthreads();
    }

    // Epilogue: scale, optional column mask (int32 flags), vectorized store
#pragma unroll
    for (int i = 0; i < TM; i++) {
        const int row = blockRow + tRow + i;
        float* crow = C + (long)row * N + blockCol + tCol;
#pragma unroll
        for (int j = 0; j < TN; j++) acc[i][j] *= scale;
        if (mask) {
#pragma unroll
            for (int j = 0; j < TN; j++)
                if (mask[blockCol + tCol + j] != 0) acc[i][j] = -FLT_MAX;
        }
        float4 v0 = make_float4(acc[i][0], acc[i][1], acc[i][2], acc[i][3]);
        float4 v1 = make_float4(acc[i][4], acc[i][5], acc[i][6], acc[i][7]);
        *reinterpret_cast<float4*>(&crow[0]) = v0;
        *reinterpret_cast<float4*>(&crow[4]) = v1;
    }
}

// ---------------------------------------------------------------------------
// Row softmax over length LL. One block (256 threads) per row; row cached in
// shared memory (16 KB).
// ---------------------------------------------------------------------------
__global__ __launch_bounds__(256)
void softmax_kernel(float* __restrict__ S)
{
    __shared__ float buf[LL];
    __shared__ float red[256];

    const int tid = threadIdx.x;
    float* p = S + (long)blockIdx.x * LL;

    float m = -FLT_MAX;
    for (int i = tid; i < LL; i += 256) {
        float v = p[i];
        buf[i] = v;
        m = fmaxf(m, v);
    }
    red[tid] = m;
    __syncthreads();
    for (int s = 128; s > 0; s >>= 1) {
        if (tid < s) red[tid] = fmaxf(red[tid], red[tid + s]);
        __syncthreads();
    }
    m = red[0];
    __syncthreads();

    float sum = 0.0f;
    for (int i = tid; i < LL; i += 256) {
        float e = __expf(buf[i] - m);
        buf[i] = e;
        sum += e;
    }
    red[tid] = sum;
    __syncthreads();
    for (int s = 128; s > 0; s >>= 1) {
        if (tid < s) red[tid] += red[tid + s];
        __syncthreads();
    }
    const float inv = 1.0f / red[0];

    for (int i = tid; i < LL; i += 256)
        p[i] = buf[i] * inv;
}

// ---------------------------------------------------------------------------
// Launch: 5 kernels, all on default stream (graph-capturable, no allocs).
// Inputs (metadata order): H [B,L,DH] f32, G [B,T,DG] f32, mask [B,L] int32,
// Wk_w [P,DH] f32, Wq_w [P,DG] f32. Output Z [B,T,DH] f32.
// ---------------------------------------------------------------------------
extern "C" void kernel_launch(void* const* d_in, const int* in_sizes, int n_in,
                              void* d_out, int out_size)
{
    const float* H    = (const float*)d_in[0];
    const float* G    = (const float*)d_in[1];
    const int*   mask = (const int*)d_in[2];
    const float* Wk   = (const float*)d_in[3];
    const float* Wq   = (const float*)d_in[4];
    float*       Z    = (float*)d_out;

    float *gK, *gQ, *gS;
    cudaGetSymbolAddress((void**)&gK, g_K);
    cudaGetSymbolAddress((void**)&gQ, g_Q);
    cudaGetSymbolAddress((void**)&gS, g_S);

    const float scaleS = 0.0625f;  // P^-0.5 = 1/16

    // 1) K = H * Wk^T : [16384,1024] x [256,1024]^T -> [16384,256]
    {
        dim3 grid(PP / BN, (BB * LL) / BM, 1);
        sgemm_kernel<true><<<grid, 256>>>(H, Wk, gK,
                                          BB * LL, PP, DH,
                                          0, 0, 0, 1.0f, nullptr, 0);
    }
    // 2) Q = G * Wq^T : [4096,768] x [256,768]^T -> [4096,256]
    {
        dim3 grid(PP / BN, (BB * TT) / BM, 1);
        sgemm_kernel<true><<<grid, 256>>>(G, Wq, gQ,
                                          BB * TT, PP, DG,
                                          0, 0, 0, 1.0f, nullptr, 0);
    }
    // 3) S = scale * Q * K^T, masked : per batch [1024,256] x [4096,256]^T
    {
        dim3 grid(LL / BN, TT / BM, BB);
        sgemm_kernel<true><<<grid, 256>>>(gQ, gK, gS,
                                          TT, LL, PP,
                                          (long)TT * PP, (long)LL * PP,
                                          (long)TT * LL,
                                          scaleS, mask, (long)LL);
    }
    // 4) softmax over L for each of B*T rows
    softmax_kernel<<<BB * TT, 256>>>(gS);

    // 5) Z = alpha * H : per batch [1024,4096] x [4096,1024] (NN)
    {
        dim3 grid(DH / BN, TT / BM, BB);
        sgemm_kernel<false><<<grid, 256>>>(gS, H, Z,
                                           TT, DH, LL,
                                           (long)TT * LL, (long)LL * DH,
                                           (long)TT * DH,
                                           1.0f, nullptr, 0);
    }
}

// round 4
// speedup vs baseline: 1.5148x; 1.5148x over previous
#include <cuda_runtime.h>
#include <cstdint>
#include <float.h>

// Problem constants
#define BB 4
#define LL 4096
#define DHQ 1024
#define TTQ 1024
#define DGQ 768
#define PPQ 256

// Scratch (__device__ globals; no cudaMalloc allowed)
__device__ float g_K[(size_t)BB * LL * PPQ];   // 16 MB
__device__ float g_Q[(size_t)BB * TTQ * PPQ];  //  4 MB
__device__ float g_S[(size_t)BB * TTQ * LL];   // 64 MB

// ---------------------------------------------------------------------------
// tf32 helpers
// ---------------------------------------------------------------------------
__device__ __forceinline__ uint32_t f2tf32(float x) {
    uint32_t r;
    asm("cvt.rna.tf32.f32 %0, %1;" : "=r"(r) : "f"(x));
    return r;
}

__device__ __forceinline__ void mma_tf32(float* d, const uint32_t* a, const uint32_t* b) {
    asm volatile(
        "mma.sync.aligned.m16n8k8.row.col.f32.tf32.tf32.f32 "
        "{%0,%1,%2,%3}, {%4,%5,%6,%7}, {%8,%9}, {%0,%1,%2,%3};"
        : "+f"(d[0]), "+f"(d[1]), "+f"(d[2]), "+f"(d[3])
        : "r"(a[0]), "r"(a[1]), "r"(a[2]), "r"(a[3]), "r"(b[0]), "r"(b[1]));
}

// ---------------------------------------------------------------------------
// tf32 tensor-core GEMM, 3xTF32 split: C[M,N] = scale * A[M,K] * op(B)
//   BT=true : B is [N,K] row-major (NT)
//   BT=false: B is [K,N] row-major (NN)
// Block tile 128x128, BK=32, 256 threads (8 warps, 64x32 warp tiles).
// Optional per-column int32 mask (logits): nonzero -> -FLT_MAX.
// SMEM per stage (floats): A_hi[128*36] A_lo[128*36] B_hi B_lo (uniform 4608 slots)
// ---------------------------------------------------------------------------
#define SLOT 4608                     // floats per operand tile slot
#define STAGE (4 * SLOT)              // floats per stage
#define SMEM_GEMM (2 * STAGE * 4)     // bytes (147456)

template <bool BT>
__global__ __launch_bounds__(256)
void tf32_mma_gemm(const float* __restrict__ A, const float* __restrict__ B,
                   float* __restrict__ C,
                   int K, long lda, long ldb, long ldc,
                   long sA, long sB, long sC,
                   float scale, const int* __restrict__ mask, long maskStride)
{
    extern __shared__ float sm[];

    const int tid  = threadIdx.x;
    const int wid  = tid >> 5;
    const int lane = tid & 31;
    const int grp  = lane >> 2;       // 0..7
    const int tig  = lane & 3;        // 0..3
    const int wm   = (wid & 1) * 64;  // warp m offset in tile
    const int wn   = (wid >> 1) * 32; // warp n offset in tile

    const int bz = blockIdx.z;
    A += (long)bz * sA;
    B += (long)bz * sB;
    C += (long)bz * sC;
    if (mask) mask += (long)bz * maskStride;

    const long row0 = (long)blockIdx.y * 128;
    const long col0 = (long)blockIdx.x * 128;

    // gmem tile loader indices
    //   A (and B when NT): 128 rows x 32 k, float4 along k: 1024 f4, 4/thread
    //   B when NN: 32 rows(k) x 128 n, float4 along n: 1024 f4, 4/thread
    float4 rA[4], rB[4];

    auto load_tile = [&](int it) {
        const float* pA = A + row0 * lda + (long)it * 32;
#pragma unroll
        for (int p = 0; p < 4; ++p) {
            const int f = p * 256 + tid;
            rA[p] = *reinterpret_cast<const float4*>(pA + (long)(f >> 3) * lda + (f & 7) * 4);
        }
        if (BT) {
            const float* pB = B + col0 * ldb + (long)it * 32;
#pragma unroll
            for (int p = 0; p < 4; ++p) {
                const int f = p * 256 + tid;
                rB[p] = *reinterpret_cast<const float4*>(pB + (long)(f >> 3) * ldb + (f & 7) * 4);
            }
        } else {
            const float* pB = B + (long)it * 32 * ldb + col0;
#pragma unroll
            for (int p = 0; p < 4; ++p) {
                const int f = p * 256 + tid;
                rB[p] = *reinterpret_cast<const float4*>(pB + (long)(f >> 5) * ldb + (f & 31) * 4);
            }
        }
    };

    auto store_tile = [&](float* st) {
        float* aH = st;
        float* aL = st + SLOT;
        float* bH = st + 2 * SLOT;
        float* bL = st + 3 * SLOT;
#pragma unroll
        for (int p = 0; p < 4; ++p) {
            const int f = p * 256 + tid;
            {   // A: [m][k] stride 36
                const int off = (f >> 3) * 36 + (f & 7) * 4;
                float4 v = rA[p];
                uint32_t hx = f2tf32(v.x), hy = f2tf32(v.y), hz = f2tf32(v.z), hw = f2tf32(v.w);
                *reinterpret_cast<uint4*>(aH + off) = make_uint4(hx, hy, hz, hw);
                uint32_t lx = f2tf32(v.x - __uint_as_float(hx));
                uint32_t ly = f2tf32(v.y - __uint_as_float(hy));
                uint32_t lz = f2tf32(v.z - __uint_as_float(hz));
                uint32_t lw = f2tf32(v.w - __uint_as_float(hw));
                *reinterpret_cast<uint4*>(aL + off) = make_uint4(lx, ly, lz, lw);
            }
            {
                const int off = BT ? ((f >> 3) * 36 + (f & 7) * 4)      // [n][k] stride 36
                                   : ((f >> 5) * 136 + (f & 31) * 4);   // [k][n] stride 136
                float4 v = rB[p];
                uint32_t hx = f2tf32(v.x), hy = f2tf32(v.y), hz = f2tf32(v.z), hw = f2tf32(v.w);
                *reinterpret_cast<uint4*>(bH + off) = make_uint4(hx, hy, hz, hw);
                uint32_t lx = f2tf32(v.x - __uint_as_float(hx));
                uint32_t ly = f2tf32(v.y - __uint_as_float(hy));
                uint32_t lz = f2tf32(v.z - __uint_as_float(hz));
                uint32_t lw = f2tf32(v.w - __uint_as_float(hw));
                *reinterpret_cast<uint4*>(bL + off) = make_uint4(lx, ly, lz, lw);
            }
        }
    };

    float acc[4][4][4];
#pragma unroll
    for (int i = 0; i < 4; ++i)
#pragma unroll
        for (int j = 0; j < 4; ++j)
#pragma unroll
            for (int r = 0; r < 4; ++r) acc[i][j][r] = 0.0f;

    const int nIter = K >> 5;   // BK = 32

    load_tile(0);
    store_tile(sm);
    __syncthreads();

    for (int it = 0; it < nIter; ++it) {
        const bool more = (it + 1 < nIter);
        if (more) load_tile(it + 1);

        const uint32_t* st = reinterpret_cast<const uint32_t*>(sm + (it & 1) * STAGE);
        const uint32_t* aH = st;
        const uint32_t* aL = st + SLOT;
        const uint32_t* bH = st + 2 * SLOT;
        const uint32_t* bL = st + 3 * SLOT;

#pragma unroll
        for (int ks = 0; ks < 4; ++ks) {
            const int c = ks * 8 + tig;
            uint32_t fAH[4][4], fAL[4][4], fBH[4][2], fBL[4][2];
#pragma unroll
            for (int i = 0; i < 4; ++i) {
                const int r = wm + i * 16 + grp;
                fAH[i][0] = aH[r * 36 + c];
                fAH[i][1] = aH[(r + 8) * 36 + c];
                fAH[i][2] = aH[r * 36 + c + 4];
                fAH[i][3] = aH[(r + 8) * 36 + c + 4];
                fAL[i][0] = aL[r * 36 + c];
                fAL[i][1] = aL[(r + 8) * 36 + c];
                fAL[i][2] = aL[r * 36 + c + 4];
                fAL[i][3] = aL[(r + 8) * 36 + c + 4];
            }
#pragma unroll
            for (int j = 0; j < 4; ++j) {
                const int n = wn + j * 8 + grp;
                if (BT) {
                    fBH[j][0] = bH[n * 36 + c];
                    fBH[j][1] = bH[n * 36 + c + 4];
                    fBL[j][0] = bL[n * 36 + c];
                    fBL[j][1] = bL[n * 36 + c + 4];
                } else {
                    fBH[j][0] = bH[c * 136 + n];
                    fBH[j][1] = bH[(c + 4) * 136 + n];
                    fBL[j][0] = bL[c * 136 + n];
                    fBL[j][1] = bL[(c + 4) * 136 + n];
                }
            }
#pragma unroll
            for (int i = 0; i < 4; ++i)
#pragma unroll
                for (int j = 0; j < 4; ++j) {
                    mma_tf32(acc[i][j], fAH[i], fBH[j]);
                    mma_tf32(acc[i][j], fAH[i], fBL[j]);
                    mma_tf32(acc[i][j], fAL[i], fBH[j]);
                }
        }

        if (more) store_tile(sm + ((it + 1) & 1) * STAGE);
        __syncthreads();
    }

    // Epilogue: direct register -> gmem (float2 per row-pair), scale + mask
#pragma unroll
    for (int i = 0; i < 4; ++i) {
        const long r0 = row0 + wm + i * 16 + grp;
#pragma unroll
        for (int j = 0; j < 4; ++j) {
            const long gc = col0 + wn + j * 8 + tig * 2;
            float x0 = acc[i][j][0] * scale, x1 = acc[i][j][1] * scale;
            float y0 = acc[i][j][2] * scale, y1 = acc[i][j][3] * scale;
            if (mask) {
                const bool m0 = mask[gc] != 0, m1 = mask[gc + 1] != 0;
                if (m0) { x0 = -FLT_MAX; y0 = -FLT_MAX; }
                if (m1) { x1 = -FLT_MAX; y1 = -FLT_MAX; }
            }
            *reinterpret_cast<float2*>(C + r0 * ldc + gc)       = make_float2(x0, x1);
            *reinterpret_cast<float2*>(C + (r0 + 8) * ldc + gc) = make_float2(y0, y1);
        }
    }
}

// ---------------------------------------------------------------------------
// Row softmax over LL
// ---------------------------------------------------------------------------
__global__ __launch_bounds__(256)
void softmax_kernel(float* __restrict__ S)
{
    __shared__ float buf[LL];
    __shared__ float red[256];

    const int tid = threadIdx.x;
    float* p = S + (long)blockIdx.x * LL;

    float m = -FLT_MAX;
    for (int i = tid; i < LL; i += 256) {
        float v = p[i];
        buf[i] = v;
        m = fmaxf(m, v);
    }
    red[tid] = m;
    __syncthreads();
    for (int s = 128; s > 0; s >>= 1) {
        if (tid < s) red[tid] = fmaxf(red[tid], red[tid + s]);
        __syncthreads();
    }
    m = red[0];
    __syncthreads();

    float sum = 0.0f;
    for (int i = tid; i < LL; i += 256) {
        float e = __expf(buf[i] - m);
        buf[i] = e;
        sum += e;
    }
    red[tid] = sum;
    __syncthreads();
    for (int s = 128; s > 0; s >>= 1) {
        if (tid < s) red[tid] += red[tid + s];
        __syncthreads();
    }
    const float inv = 1.0f / red[0];

    for (int i = tid; i < LL; i += 256)
        p[i] = buf[i] * inv;
}

// ---------------------------------------------------------------------------
// Launch. Inputs: H [B,L,DH] f32, G [B,T,DG] f32, mask [B,L] int32,
// Wk_w [P,DH] f32, Wq_w [P,DG] f32. Output Z [B,T,DH] f32.
// ---------------------------------------------------------------------------
extern "C" void kernel_launch(void* const* d_in, const int* in_sizes, int n_in,
                              void* d_out, int out_size)
{
    const float* H    = (const float*)d_in[0];
    const float* G    = (const float*)d_in[1];
    const int*   mask = (const int*)d_in[2];
    const float* Wk   = (const float*)d_in[3];
    const float* Wq   = (const float*)d_in[4];
    float*       Z    = (float*)d_out;

    float *gK, *gQ, *gS;
    cudaGetSymbolAddress((void**)&gK, g_K);
    cudaGetSymbolAddress((void**)&gQ, g_Q);
    cudaGetSymbolAddress((void**)&gS, g_S);

    cudaFuncSetAttribute(tf32_mma_gemm<true>,
                         cudaFuncAttributeMaxDynamicSharedMemorySize, SMEM_GEMM);
    cudaFuncSetAttribute(tf32_mma_gemm<false>,
                         cudaFuncAttributeMaxDynamicSharedMemorySize, SMEM_GEMM);

    // 1) K = H * Wk^T : [B*L, DH] x [P, DH]^T -> [B*L, P]
    tf32_mma_gemm<true><<<dim3(PPQ / 128, (BB * LL) / 128, 1), 256, SMEM_GEMM>>>(
        H, Wk, gK, DHQ, DHQ, DHQ, PPQ, 0, 0, 0, 1.0f, nullptr, 0);

    // 2) Q = G * Wq^T : [B*T, DG] x [P, DG]^T -> [B*T, P]
    tf32_mma_gemm<true><<<dim3(PPQ / 128, (BB * TTQ) / 128, 1), 256, SMEM_GEMM>>>(
        G, Wq, gQ, DGQ, DGQ, DGQ, PPQ, 0, 0, 0, 1.0f, nullptr, 0);

    // 3) S = scale * Q * K^T (masked) : per batch [T, P] x [L, P]^T -> [T, L]
    tf32_mma_gemm<true><<<dim3(LL / 128, TTQ / 128, BB), 256, SMEM_GEMM>>>(
        gQ, gK, gS, PPQ, PPQ, PPQ, LL,
        (long)TTQ * PPQ, (long)LL * PPQ, (long)TTQ * LL,
        0.0625f, mask, (long)LL);

    // 4) softmax over L
    softmax_kernel<<<BB * TTQ, 256>>>(gS);

    // 5) Z = alpha * H : per batch [T, L] x [L, DH] (NN) -> [T, DH]
    tf32_mma_gemm<false><<<dim3(DHQ / 128, TTQ / 128, BB), 256, SMEM_GEMM>>>(
        gS, H, Z, LL, LL, DHQ, DHQ,
        (long)TTQ * LL, (long)LL * DHQ, (long)TTQ * DHQ,
        1.0f, nullptr, 0);
}